// round 3
// baseline (speedup 1.0000x reference)
#include <cuda_runtime.h>
#include <math.h>

// ---------------- problem constants ----------------
#define BB   64          // batch
#define NN   256         // sequence length (K in reference)
#define CC   512         // input channels
#define OO   1024        // qkv channels (2*OUT_PLANES)
#define GG   8           // groups
#define HC   32          // half group planes (q/k channels per group)
#define VC   64          // v channels per group
#define EPSV 1e-5f
#define F_QR 0.1f
#define F_KR 0.1f
#define F_SVE 0.1f
#define F_SV  1.0f

// ---------------- scratch (static device allocations) ----------------
__device__ float d_qkv[(size_t)BB * OO * NN];                 // 64 MB
__device__ float d_bnA[OO];
__device__ float d_bnC[OO];
__device__ float d_stk[(size_t)3 * BB * GG * NN * NN];        // 402 MB (qk,qr,kr raw)
__device__ float d_simstats[48];                              // 24 ch x (sum,sumsq)
__device__ float d_sv [(size_t)BB * GG * VC * NN];            // 33.5 MB
__device__ float d_sve[(size_t)BB * GG * VC * NN];            // 33.5 MB
__device__ float d_outA[OO];
__device__ float d_outC[OO];

// ---------------- K0: zero sim stats (must run every replay) ----------------
__global__ void k_zero_stats() {
    int t = threadIdx.x;
    if (t < 48) d_simstats[t] = 0.0f;
}

// ---------------- K1: qkv GEMM  qkv[b][o][n] = sum_c w[o][c]*x[b][n][c] ----------------
#define GM 64
#define GN 64
#define GK 16
__global__ void k_qkv_gemm(const float* __restrict__ x, const float* __restrict__ w) {
    __shared__ float Xs[GK][GM + 4];
    __shared__ float Ws[GK][GN + 4];
    int b  = blockIdx.z;
    int n0 = blockIdx.x * GM;
    int o0 = blockIdx.y * GN;
    int tid = threadIdx.x;
    int tx = tid & 15, ty = tid >> 4;
    float acc[4][4];
#pragma unroll
    for (int i = 0; i < 4; i++)
#pragma unroll
        for (int j = 0; j < 4; j++) acc[i][j] = 0.0f;

    const float* xb = x + ((size_t)b * NN + n0) * CC;
    int lr = tid >> 2;            // 0..63
    int lc = (tid & 3) * 4;       // 0,4,8,12

    for (int c0 = 0; c0 < CC; c0 += GK) {
        float4 v = *(const float4*)(xb + (size_t)lr * CC + c0 + lc);
        Xs[lc + 0][lr] = v.x; Xs[lc + 1][lr] = v.y; Xs[lc + 2][lr] = v.z; Xs[lc + 3][lr] = v.w;
        float4 u = *(const float4*)(w + (size_t)(o0 + lr) * CC + c0 + lc);
        Ws[lc + 0][lr] = u.x; Ws[lc + 1][lr] = u.y; Ws[lc + 2][lr] = u.z; Ws[lc + 3][lr] = u.w;
        __syncthreads();
#pragma unroll
        for (int kk = 0; kk < GK; kk++) {
            float4 a4 = *(const float4*)&Xs[kk][tx * 4];
            float4 b4 = *(const float4*)&Ws[kk][ty * 4];
            float a[4] = {a4.x, a4.y, a4.z, a4.w};
            float bbv[4] = {b4.x, b4.y, b4.z, b4.w};
#pragma unroll
            for (int j = 0; j < 4; j++)
#pragma unroll
                for (int i = 0; i < 4; i++) acc[j][i] += a[i] * bbv[j];
        }
        __syncthreads();
    }
    float* outp = d_qkv + ((size_t)b * OO + o0) * NN + n0;
#pragma unroll
    for (int j = 0; j < 4; j++) {
        float4 v = make_float4(acc[j][0], acc[j][1], acc[j][2], acc[j][3]);
        *(float4*)(outp + (size_t)(ty * 4 + j) * NN + tx * 4) = v;
    }
}

// ---------------- block reduce helper ----------------
__device__ __forceinline__ void block_reduce2(float& s, float& ss, float* sh) {
    int tid = threadIdx.x;
    float* shs = sh;         // 256
    float* shq = sh + 256;   // 256
    shs[tid] = s; shq[tid] = ss;
    __syncthreads();
    for (int step = 128; step > 0; step >>= 1) {
        if (tid < step) { shs[tid] += shs[tid + step]; shq[tid] += shq[tid + step]; }
        __syncthreads();
    }
    s = shs[0]; ss = shq[0];
}

// ---------------- K2: qkv BN -> per-channel affine ----------------
__global__ void k_qkv_stats(const float* __restrict__ gq, const float* __restrict__ bq) {
    __shared__ float sh[512];
    int o = blockIdx.x;
    int tid = threadIdx.x;     // n index
    float s = 0.f, ss = 0.f;
    const float* base = d_qkv + (size_t)o * NN + tid;
    for (int b = 0; b < BB; b++) {
        float v = base[(size_t)b * OO * NN];
        s += v; ss += v * v;
    }
    block_reduce2(s, ss, sh);
    if (tid == 0) {
        float m = s / 16384.0f;
        float var = ss / 16384.0f - m * m;
        float a = gq[o] * rsqrtf(var + EPSV);
        d_bnA[o] = a;
        d_bnC[o] = bq[o] - m * a;
    }
}

// ---------------- K3: raw qk/qr/kr + channel stats ----------------
// grid (4 itiles of 64, G, B), 256 threads (thread = j)
__global__ void k_sim_raw(const float* __restrict__ rel) {
    extern __shared__ float sm[];
    float* qs   = sm;                 // 32*64
    float* relA = qs + 32 * 64;       // 32*320
    float* relB = relA + 32 * 320;    // 32*320
    int it = blockIdx.x, g = blockIdx.y, b = blockIdx.z;
    int i0 = it * 64;
    int tid = threadIdx.x;

    for (int idx = tid; idx < 32 * 319; idx += 256) {
        int c = idx / 319, d = idx - c * 319;
        relA[c * 320 + d] = rel[(size_t)c * 511 + i0 + d];
        relB[c * 320 + d] = rel[(size_t)(32 + c) * 511 + (192 - i0) + d];
    }
    {
        int cbase = tid >> 6, il = tid & 63;
        for (int c = cbase; c < 32; c += 4) {
            int o = g * 128 + c;
            qs[c * 64 + il] = d_bnA[o] * d_qkv[((size_t)b * OO + o) * NN + i0 + il] + d_bnC[o];
        }
    }
    float kcol[32];
#pragma unroll
    for (int c = 0; c < 32; c++) {
        int o = g * 128 + HC + c;
        kcol[c] = d_bnA[o] * d_qkv[((size_t)b * OO + o) * NN + tid] + d_bnC[o];
    }
    __syncthreads();

    float s0 = 0, q0 = 0, s1 = 0, q1 = 0, s2 = 0, q2 = 0;
    const size_t F = (size_t)BB * GG * NN * NN;
    size_t base = (((size_t)b * GG + g) * NN + i0) * NN + tid;

    for (int il = 0; il < 64; il++) {
        float aqk = 0.f, aqr = 0.f, akr = 0.f;
        const float* ra = relA + (il + 255 - tid);
        const float* rb = relB + (tid - il + 63);
#pragma unroll
        for (int c = 0; c < 32; c++) {
            float qv = qs[c * 64 + il];
            aqk += qv * kcol[c];
            aqr += qv * ra[c * 320];
            akr += kcol[c] * rb[c * 320];
        }
        aqr *= F_QR; akr *= F_KR;
        size_t off = base + (size_t)il * NN;
        d_stk[off]         = aqk;
        d_stk[F + off]     = aqr;
        d_stk[2 * F + off] = akr;
        s0 += aqk; q0 += aqk * aqk;
        s1 += aqr; q1 += aqr * aqr;
        s2 += akr; q2 += akr * akr;
    }
#pragma unroll
    for (int off = 16; off; off >>= 1) {
        s0 += __shfl_xor_sync(0xffffffffu, s0, off);
        q0 += __shfl_xor_sync(0xffffffffu, q0, off);
        s1 += __shfl_xor_sync(0xffffffffu, s1, off);
        q1 += __shfl_xor_sync(0xffffffffu, q1, off);
        s2 += __shfl_xor_sync(0xffffffffu, s2, off);
        q2 += __shfl_xor_sync(0xffffffffu, q2, off);
    }
    if ((tid & 31) == 0) {
        atomicAdd(&d_simstats[(0 * 8 + g) * 2],     s0);
        atomicAdd(&d_simstats[(0 * 8 + g) * 2 + 1], q0);
        atomicAdd(&d_simstats[(1 * 8 + g) * 2],     s1);
        atomicAdd(&d_simstats[(1 * 8 + g) * 2 + 1], q1);
        atomicAdd(&d_simstats[(2 * 8 + g) * 2],     s2);
        atomicAdd(&d_simstats[(2 * 8 + g) * 2 + 1], q2);
    }
}

// ---------------- K5: sim BN + softmax + sv + sve ----------------
// grid (8 itiles of 32, G, B), 256 threads
__global__ void k_attn(const float* __restrict__ rel,
                       const float* __restrict__ gsim, const float* __restrict__ bsim) {
    extern __shared__ float sm[];
    float* p    = sm;                   // 32*257
    float* vbs  = p + 32 * 257;         // 64*257
    float* relV = vbs + 64 * 257;       // 64*287
    float* stage = relV + 64 * 287;     // 64*33
    int it = blockIdx.x, g = blockIdx.y, b = blockIdx.z;
    int i0 = it * 32;
    int tid = threadIdx.x;

    const float NELI = 1.0f / (64.0f * 256.0f * 256.0f);
    float aS[3], cS[3];
#pragma unroll
    for (int s = 0; s < 3; s++) {
        int ch = s * 8 + g;
        float m = d_simstats[ch * 2] * NELI;
        float var = d_simstats[ch * 2 + 1] * NELI - m * m;
        float a = gsim[ch] * rsqrtf(var + EPSV);
        aS[s] = a; cS[s] = bsim[ch] - m * a;
    }

    const size_t F = (size_t)BB * GG * NN * NN;
    size_t baseL = (((size_t)b * GG + g) * NN + i0) * NN + tid;
    for (int il = 0; il < 32; il++) {
        size_t off = baseL + (size_t)il * NN;
        float L = aS[0] * d_stk[off] + cS[0]
                + aS[1] * d_stk[F + off] + cS[1]
                + aS[2] * d_stk[2 * F + off] + cS[2];
        p[il * 257 + tid] = L;
    }
    for (int c = 0; c < VC; c++) {
        int o = g * 128 + 2 * HC + c;
        vbs[c * 257 + tid] = d_bnA[o] * d_qkv[((size_t)b * OO + o) * NN + tid] + d_bnC[o];
    }
    for (int idx = tid; idx < 64 * 287; idx += 256) {
        int c = idx / 287, d = idx - c * 287;
        relV[idx] = rel[(size_t)(64 + c) * 511 + i0 + d];
    }
    __syncthreads();

    // softmax over j, one warp handles 4 rows
    int warp = tid >> 5, lane = tid & 31;
    for (int r = warp; r < 32; r += 8) {
        float* row = p + r * 257;
        float v[8];
        float mx = -1e30f;
#pragma unroll
        for (int k = 0; k < 8; k++) { v[k] = row[lane + 32 * k]; mx = fmaxf(mx, v[k]); }
#pragma unroll
        for (int off = 16; off; off >>= 1) mx = fmaxf(mx, __shfl_xor_sync(0xffffffffu, mx, off));
        float sum = 0.f;
#pragma unroll
        for (int k = 0; k < 8; k++) { v[k] = expf(v[k] - mx); sum += v[k]; }
#pragma unroll
        for (int off = 16; off; off >>= 1) sum += __shfl_xor_sync(0xffffffffu, sum, off);
        float inv = 1.0f / sum;
#pragma unroll
        for (int k = 0; k < 8; k++) row[lane + 32 * k] = v[k] * inv;
    }
    __syncthreads();

    // sv / sve : thread -> (c = tid%64, il = tid/64 + 4k)
    int c = tid & 63;
    int il0 = tid >> 6;
    float asv[8], asve[8];
#pragma unroll
    for (int k = 0; k < 8; k++) { asv[k] = 0.f; asve[k] = 0.f; }
    for (int j = 0; j < 256; j++) {
        float vb = vbs[c * 257 + j];
#pragma unroll
        for (int k = 0; k < 8; k++) {
            int il = il0 + 4 * k;
            float pv = p[il * 257 + j];
            asv[k]  += pv * vb;
            asve[k] += pv * relV[c * 287 + il + 255 - j];
        }
    }
    size_t baseO = (((size_t)b * GG + g) * VC) * NN + i0;

#pragma unroll
    for (int k = 0; k < 8; k++) stage[c * 33 + il0 + 4 * k] = asv[k] * F_SV;
    __syncthreads();
    for (int idx = tid; idx < 2048; idx += 256) {
        int cc = idx >> 5, ii = idx & 31;
        d_sv[baseO + (size_t)cc * NN + ii] = stage[cc * 33 + ii];
    }
    __syncthreads();
#pragma unroll
    for (int k = 0; k < 8; k++) stage[c * 33 + il0 + 4 * k] = asve[k] * F_SVE;
    __syncthreads();
    for (int idx = tid; idx < 2048; idx += 256) {
        int cc = idx >> 5, ii = idx & 31;
        d_sve[baseO + (size_t)cc * NN + ii] = stage[cc * 33 + ii];
    }
}

// ---------------- K6: out BN stats ----------------
__global__ void k_out_stats(const float* __restrict__ gout, const float* __restrict__ bout) {
    __shared__ float sh[512];
    int ch = blockIdx.x;                  // 0..1023 : ch = g*128 + c*2 + t
    int g = ch >> 7, rem = ch & 127, c = rem >> 1, t = rem & 1;
    int tid = threadIdx.x;                // i index
    const float* src = (t ? d_sve : d_sv) + (((size_t)g) * VC + c) * NN + tid;
    float s = 0.f, ss = 0.f;
    for (int b = 0; b < BB; b++) {
        float v = src[(size_t)b * GG * VC * NN];
        s += v; ss += v * v;
    }
    block_reduce2(s, ss, sh);
    if (tid == 0) {
        float m = s / 16384.0f;
        float var = ss / 16384.0f - m * m;
        float a = gout[ch] * rsqrtf(var + EPSV);
        d_outA[ch] = a;
        d_outC[ch] = bout[ch] - m * a;
    }
}

// ---------------- K7: final combine ----------------
__global__ void k_final(float* __restrict__ out) {
    size_t idx = (size_t)blockIdx.x * 256 + threadIdx.x;   // 64*512*256
    int n = idx & 255;
    int pch = (int)((idx >> 8) & 511);
    int b = (int)(idx >> 17);
    int g = pch >> 6, c = pch & 63;
    size_t si = (((size_t)b * GG + g) * VC + c) * NN + n;
    float sv = d_sv[si], sve = d_sve[si];
    int ch0 = pch * 2, ch1 = ch0 + 1;
    out[idx] = d_outA[ch0] * sv + d_outC[ch0] + d_outA[ch1] * sve + d_outC[ch1];
}

// ---------------- launch ----------------
extern "C" void kernel_launch(void* const* d_in, const int* in_sizes, int n_in,
                              void* d_out, int out_size) {
    const float* x    = (const float*)d_in[0];
    const float* wqkv = (const float*)d_in[1];
    const float* rel  = (const float*)d_in[2];
    const float* gq   = (const float*)d_in[3];
    const float* bq   = (const float*)d_in[4];
    const float* gs   = (const float*)d_in[5];
    const float* bs   = (const float*)d_in[6];
    const float* go   = (const float*)d_in[7];
    const float* bo   = (const float*)d_in[8];
    float* out = (float*)d_out;

    size_t smemK3 = (size_t)(32 * 64 + 2 * 32 * 320) * sizeof(float);          // 90112 B
    size_t smemK5 = (size_t)(32 * 257 + 64 * 257 + 64 * 287 + 64 * 33) * sizeof(float); // ~180.6 KB
    cudaFuncSetAttribute(k_sim_raw, cudaFuncAttributeMaxDynamicSharedMemorySize, (int)smemK3);
    cudaFuncSetAttribute(k_attn,    cudaFuncAttributeMaxDynamicSharedMemorySize, (int)smemK5);

    k_zero_stats<<<1, 64>>>();
    {
        dim3 grid(NN / GM, OO / GN, BB);
        k_qkv_gemm<<<grid, 256>>>(x, wqkv);
    }
    k_qkv_stats<<<OO, 256>>>(gq, bq);
    {
        dim3 grid(4, GG, BB);
        k_sim_raw<<<grid, 256, smemK3>>>(rel);
    }
    {
        dim3 grid(8, GG, BB);
        k_attn<<<grid, 256, smemK5>>>(rel, gs, bs);
    }
    k_out_stats<<<OO, 256>>>(go, bo);
    {
        size_t total = (size_t)BB * 512 * NN;
        k_final<<<(unsigned)(total / 256), 256>>>(out);
    }
}

// round 4
// speedup vs baseline: 1.5407x; 1.5407x over previous
#include <cuda_runtime.h>
#include <math.h>

// ---------------- problem constants ----------------
#define BB   64          // batch
#define NN   256         // sequence length (K in reference)
#define CC   512         // input channels
#define OO   1024        // qkv channels (2*OUT_PLANES)
#define GG   8           // groups
#define HC   32          // half group planes (q/k channels per group)
#define VC   64          // v channels per group
#define EPSV 1e-5f
#define F_QR 0.1f
#define F_KR 0.1f
#define F_SVE 0.1f
#define F_SV  1.0f

// ---------------- scratch (static device allocations) ----------------
__device__ float d_qkv[(size_t)BB * OO * NN];                 // 64 MB
__device__ float d_bnA[OO];
__device__ float d_bnC[OO];
__device__ float d_stk[(size_t)3 * BB * GG * NN * NN];        // 402 MB (qk,qr,kr raw)
__device__ float d_simstats[48];                              // 24 ch x (sum,sumsq)
__device__ float d_sv [(size_t)BB * GG * VC * NN];            // 33.5 MB
__device__ float d_sve[(size_t)BB * GG * VC * NN];            // 33.5 MB
__device__ float d_outA[OO];
__device__ float d_outC[OO];

// ---------------- K0: zero sim stats (must run every replay) ----------------
__global__ void k_zero_stats() {
    int t = threadIdx.x;
    if (t < 48) d_simstats[t] = 0.0f;
}

// ---------------- K1: qkv GEMM  qkv[b][o][n] = sum_c w[o][c]*x[b][n][c] ----------------
#define GM 64
#define GN 64
#define GK 16
__global__ void k_qkv_gemm(const float* __restrict__ x, const float* __restrict__ w) {
    __shared__ float Xs[GK][GM + 4];
    __shared__ float Ws[GK][GN + 4];
    int b  = blockIdx.z;
    int n0 = blockIdx.x * GM;
    int o0 = blockIdx.y * GN;
    int tid = threadIdx.x;
    int tx = tid & 15, ty = tid >> 4;
    float acc[4][4];
#pragma unroll
    for (int i = 0; i < 4; i++)
#pragma unroll
        for (int j = 0; j < 4; j++) acc[i][j] = 0.0f;

    const float* xb = x + ((size_t)b * NN + n0) * CC;
    int lr = tid >> 2;            // 0..63
    int lc = (tid & 3) * 4;       // 0,4,8,12

    for (int c0 = 0; c0 < CC; c0 += GK) {
        float4 v = *(const float4*)(xb + (size_t)lr * CC + c0 + lc);
        Xs[lc + 0][lr] = v.x; Xs[lc + 1][lr] = v.y; Xs[lc + 2][lr] = v.z; Xs[lc + 3][lr] = v.w;
        float4 u = *(const float4*)(w + (size_t)(o0 + lr) * CC + c0 + lc);
        Ws[lc + 0][lr] = u.x; Ws[lc + 1][lr] = u.y; Ws[lc + 2][lr] = u.z; Ws[lc + 3][lr] = u.w;
        __syncthreads();
#pragma unroll
        for (int kk = 0; kk < GK; kk++) {
            float4 a4 = *(const float4*)&Xs[kk][tx * 4];
            float4 b4 = *(const float4*)&Ws[kk][ty * 4];
            float a[4] = {a4.x, a4.y, a4.z, a4.w};
            float bbv[4] = {b4.x, b4.y, b4.z, b4.w};
#pragma unroll
            for (int j = 0; j < 4; j++)
#pragma unroll
                for (int i = 0; i < 4; i++) acc[j][i] += a[i] * bbv[j];
        }
        __syncthreads();
    }
    float* outp = d_qkv + ((size_t)b * OO + o0) * NN + n0;
#pragma unroll
    for (int j = 0; j < 4; j++) {
        float4 v = make_float4(acc[j][0], acc[j][1], acc[j][2], acc[j][3]);
        *(float4*)(outp + (size_t)(ty * 4 + j) * NN + tx * 4) = v;
    }
}

// ---------------- block reduce helper ----------------
__device__ __forceinline__ void block_reduce2(float& s, float& ss, float* sh) {
    int tid = threadIdx.x;
    float* shs = sh;         // 256
    float* shq = sh + 256;   // 256
    shs[tid] = s; shq[tid] = ss;
    __syncthreads();
    for (int step = 128; step > 0; step >>= 1) {
        if (tid < step) { shs[tid] += shs[tid + step]; shq[tid] += shq[tid + step]; }
        __syncthreads();
    }
    s = shs[0]; ss = shq[0];
}

// ---------------- K2: qkv BN -> per-channel affine ----------------
__global__ void k_qkv_stats(const float* __restrict__ gq, const float* __restrict__ bq) {
    __shared__ float sh[512];
    int o = blockIdx.x;
    int tid = threadIdx.x;     // n index
    float s = 0.f, ss = 0.f;
    const float* base = d_qkv + (size_t)o * NN + tid;
    for (int b = 0; b < BB; b++) {
        float v = base[(size_t)b * OO * NN];
        s += v; ss += v * v;
    }
    block_reduce2(s, ss, sh);
    if (tid == 0) {
        float m = s / 16384.0f;
        float var = ss / 16384.0f - m * m;
        float a = gq[o] * rsqrtf(var + EPSV);
        d_bnA[o] = a;
        d_bnC[o] = bq[o] - m * a;
    }
}

// ---------------- K3: raw qk/qr/kr + channel stats ----------------
// grid (4 itiles of 64, G, B), 256 threads (thread = j)
__global__ void k_sim_raw(const float* __restrict__ rel) {
    extern __shared__ float sm[];
    float* qs   = sm;                 // 32*64
    float* relA = qs + 32 * 64;       // 32*320
    float* relB = relA + 32 * 320;    // 32*320
    int it = blockIdx.x, g = blockIdx.y, b = blockIdx.z;
    int i0 = it * 64;
    int tid = threadIdx.x;

    for (int idx = tid; idx < 32 * 319; idx += 256) {
        int c = idx / 319, d = idx - c * 319;
        relA[c * 320 + d] = rel[(size_t)c * 511 + i0 + d];
        relB[c * 320 + d] = rel[(size_t)(32 + c) * 511 + (192 - i0) + d];
    }
    {
        int cbase = tid >> 6, il = tid & 63;
        for (int c = cbase; c < 32; c += 4) {
            int o = g * 128 + c;
            qs[c * 64 + il] = d_bnA[o] * d_qkv[((size_t)b * OO + o) * NN + i0 + il] + d_bnC[o];
        }
    }
    float kcol[32];
#pragma unroll
    for (int c = 0; c < 32; c++) {
        int o = g * 128 + HC + c;
        kcol[c] = d_bnA[o] * d_qkv[((size_t)b * OO + o) * NN + tid] + d_bnC[o];
    }
    __syncthreads();

    float s0 = 0, q0 = 0, s1 = 0, q1 = 0, s2 = 0, q2 = 0;
    const size_t F = (size_t)BB * GG * NN * NN;
    size_t base = (((size_t)b * GG + g) * NN + i0) * NN + tid;

    for (int il = 0; il < 64; il++) {
        float aqk = 0.f, aqr = 0.f, akr = 0.f;
        const float* ra = relA + (il + 255 - tid);
        const float* rb = relB + (tid - il + 63);
#pragma unroll
        for (int c = 0; c < 32; c++) {
            float qv = qs[c * 64 + il];
            aqk += qv * kcol[c];
            aqr += qv * ra[c * 320];
            akr += kcol[c] * rb[c * 320];
        }
        aqr *= F_QR; akr *= F_KR;
        size_t off = base + (size_t)il * NN;
        d_stk[off]         = aqk;
        d_stk[F + off]     = aqr;
        d_stk[2 * F + off] = akr;
        s0 += aqk; q0 += aqk * aqk;
        s1 += aqr; q1 += aqr * aqr;
        s2 += akr; q2 += akr * akr;
    }
#pragma unroll
    for (int off = 16; off; off >>= 1) {
        s0 += __shfl_xor_sync(0xffffffffu, s0, off);
        q0 += __shfl_xor_sync(0xffffffffu, q0, off);
        s1 += __shfl_xor_sync(0xffffffffu, s1, off);
        q1 += __shfl_xor_sync(0xffffffffu, q1, off);
        s2 += __shfl_xor_sync(0xffffffffu, s2, off);
        q2 += __shfl_xor_sync(0xffffffffu, q2, off);
    }
    if ((tid & 31) == 0) {
        atomicAdd(&d_simstats[(0 * 8 + g) * 2],     s0);
        atomicAdd(&d_simstats[(0 * 8 + g) * 2 + 1], q0);
        atomicAdd(&d_simstats[(1 * 8 + g) * 2],     s1);
        atomicAdd(&d_simstats[(1 * 8 + g) * 2 + 1], q1);
        atomicAdd(&d_simstats[(2 * 8 + g) * 2],     s2);
        atomicAdd(&d_simstats[(2 * 8 + g) * 2 + 1], q2);
    }
}

// ---------------- K5: sim BN + softmax + sv + sve ----------------
// grid (8 itiles of 32, G, B), 256 threads
__global__ void k_attn(const float* __restrict__ rel,
                       const float* __restrict__ gsim, const float* __restrict__ bsim) {
    extern __shared__ float sm[];
    float* p    = sm;                   // 32*257
    float* vbs  = p + 32 * 257;         // 64*257
    float* relV = vbs + 64 * 257;       // 64*287
    float* stage = relV + 64 * 287;     // 64*33
    int it = blockIdx.x, g = blockIdx.y, b = blockIdx.z;
    int i0 = it * 32;
    int tid = threadIdx.x;

    const float NELI = 1.0f / (64.0f * 256.0f * 256.0f);
    float aS[3], cS[3];
#pragma unroll
    for (int s = 0; s < 3; s++) {
        int ch = s * 8 + g;
        float m = d_simstats[ch * 2] * NELI;
        float var = d_simstats[ch * 2 + 1] * NELI - m * m;
        float a = gsim[ch] * rsqrtf(var + EPSV);
        aS[s] = a; cS[s] = bsim[ch] - m * a;
    }

    const size_t F = (size_t)BB * GG * NN * NN;
    size_t baseL = (((size_t)b * GG + g) * NN + i0) * NN + tid;
    for (int il = 0; il < 32; il++) {
        size_t off = baseL + (size_t)il * NN;
        float L = aS[0] * d_stk[off] + cS[0]
                + aS[1] * d_stk[F + off] + cS[1]
                + aS[2] * d_stk[2 * F + off] + cS[2];
        p[il * 257 + tid] = L;
    }
    for (int c = 0; c < VC; c++) {
        int o = g * 128 + 2 * HC + c;
        vbs[c * 257 + tid] = d_bnA[o] * d_qkv[((size_t)b * OO + o) * NN + tid] + d_bnC[o];
    }
    for (int idx = tid; idx < 64 * 287; idx += 256) {
        int c = idx / 287, d = idx - c * 287;
        relV[idx] = rel[(size_t)(64 + c) * 511 + i0 + d];
    }
    __syncthreads();

    // softmax over j, one warp handles 4 rows
    int warp = tid >> 5, lane = tid & 31;
    for (int r = warp; r < 32; r += 8) {
        float* row = p + r * 257;
        float v[8];
        float mx = -1e30f;
#pragma unroll
        for (int k = 0; k < 8; k++) { v[k] = row[lane + 32 * k]; mx = fmaxf(mx, v[k]); }
#pragma unroll
        for (int off = 16; off; off >>= 1) mx = fmaxf(mx, __shfl_xor_sync(0xffffffffu, mx, off));
        float sum = 0.f;
#pragma unroll
        for (int k = 0; k < 8; k++) { v[k] = expf(v[k] - mx); sum += v[k]; }
#pragma unroll
        for (int off = 16; off; off >>= 1) sum += __shfl_xor_sync(0xffffffffu, sum, off);
        float inv = 1.0f / sum;
#pragma unroll
        for (int k = 0; k < 8; k++) row[lane + 32 * k] = v[k] * inv;
    }
    __syncthreads();

    // sv / sve : thread -> (c = tid%64, il = tid/64 + 4k)
    int c = tid & 63;
    int il0 = tid >> 6;
    float asv[8], asve[8];
#pragma unroll
    for (int k = 0; k < 8; k++) { asv[k] = 0.f; asve[k] = 0.f; }
    for (int j = 0; j < 256; j++) {
        float vb = vbs[c * 257 + j];
#pragma unroll
        for (int k = 0; k < 8; k++) {
            int il = il0 + 4 * k;
            float pv = p[il * 257 + j];
            asv[k]  += pv * vb;
            asve[k] += pv * relV[c * 287 + il + 255 - j];
        }
    }
    size_t baseO = (((size_t)b * GG + g) * VC) * NN + i0;

#pragma unroll
    for (int k = 0; k < 8; k++) stage[c * 33 + il0 + 4 * k] = asv[k] * F_SV;
    __syncthreads();
    for (int idx = tid; idx < 2048; idx += 256) {
        int cc = idx >> 5, ii = idx & 31;
        d_sv[baseO + (size_t)cc * NN + ii] = stage[cc * 33 + ii];
    }
    __syncthreads();
#pragma unroll
    for (int k = 0; k < 8; k++) stage[c * 33 + il0 + 4 * k] = asve[k] * F_SVE;
    __syncthreads();
    for (int idx = tid; idx < 2048; idx += 256) {
        int cc = idx >> 5, ii = idx & 31;
        d_sve[baseO + (size_t)cc * NN + ii] = stage[cc * 33 + ii];
    }
}

// ---------------- K6: out BN stats ----------------
__global__ void k_out_stats(const float* __restrict__ gout, const float* __restrict__ bout) {
    __shared__ float sh[512];
    int ch = blockIdx.x;                  // 0..1023 : ch = g*128 + c*2 + t
    int g = ch >> 7, rem = ch & 127, c = rem >> 1, t = rem & 1;
    int tid = threadIdx.x;                // i index
    const float* src = (t ? d_sve : d_sv) + (((size_t)g) * VC + c) * NN + tid;
    float s = 0.f, ss = 0.f;
    for (int b = 0; b < BB; b++) {
        float v = src[(size_t)b * GG * VC * NN];
        s += v; ss += v * v;
    }
    block_reduce2(s, ss, sh);
    if (tid == 0) {
        float m = s / 16384.0f;
        float var = ss / 16384.0f - m * m;
        float a = gout[ch] * rsqrtf(var + EPSV);
        d_outA[ch] = a;
        d_outC[ch] = bout[ch] - m * a;
    }
}

// ---------------- K7: final combine ----------------
__global__ void k_final(float* __restrict__ out) {
    size_t idx = (size_t)blockIdx.x * 256 + threadIdx.x;   // 64*512*256
    int n = idx & 255;
    int pch = (int)((idx >> 8) & 511);
    int b = (int)(idx >> 17);
    int g = pch >> 6, c = pch & 63;
    size_t si = (((size_t)b * GG + g) * VC + c) * NN + n;
    float sv = d_sv[si], sve = d_sve[si];
    int ch0 = pch * 2, ch1 = ch0 + 1;
    out[idx] = d_outA[ch0] * sv + d_outC[ch0] + d_outA[ch1] * sve + d_outC[ch1];
}

// ---------------- launch ----------------
extern "C" void kernel_launch(void* const* d_in, const int* in_sizes, int n_in,
                              void* d_out, int out_size) {
    const float* x    = (const float*)d_in[0];
    const float* wqkv = (const float*)d_in[1];
    const float* rel  = (const float*)d_in[2];
    const float* gq   = (const float*)d_in[3];
    const float* bq   = (const float*)d_in[4];
    const float* gs   = (const float*)d_in[5];
    const float* bs   = (const float*)d_in[6];
    const float* go   = (const float*)d_in[7];
    const float* bo   = (const float*)d_in[8];
    float* out = (float*)d_out;

    size_t smemK3 = (size_t)(32 * 64 + 2 * 32 * 320) * sizeof(float);          // 90112 B
    size_t smemK5 = (size_t)(32 * 257 + 64 * 257 + 64 * 287 + 64 * 33) * sizeof(float); // ~180.6 KB
    cudaFuncSetAttribute(k_sim_raw, cudaFuncAttributeMaxDynamicSharedMemorySize, (int)smemK3);
    cudaFuncSetAttribute(k_attn,    cudaFuncAttributeMaxDynamicSharedMemorySize, (int)smemK5);

    k_zero_stats<<<1, 64>>>();
    {
        dim3 grid(NN / GM, OO / GN, BB);
        k_qkv_gemm<<<grid, 256>>>(x, wqkv);
    }
    k_qkv_stats<<<OO, 256>>>(gq, bq);
    {
        dim3 grid(4, GG, BB);
        k_sim_raw<<<grid, 256, smemK3>>>(rel);
    }
    {
        dim3 grid(8, GG, BB);
        k_attn<<<grid, 256, smemK5>>>(rel, gs, bs);
    }
    k_out_stats<<<OO, 256>>>(go, bo);
    {
        size_t total = (size_t)BB * 512 * NN;
        k_final<<<(unsigned)(total / 256), 256>>>(out);
    }
}

// round 5
// speedup vs baseline: 1.6121x; 1.0463x over previous
#include <cuda_runtime.h>
#include <cuda_fp16.h>
#include <math.h>

// ---------------- problem constants ----------------
#define BB   64          // batch
#define NN   256         // sequence length (K in reference)
#define CC   512         // input channels
#define OO   1024        // qkv channels (2*OUT_PLANES)
#define GG   8           // groups
#define HC   32          // half group planes (q/k channels per group)
#define VC   64          // v channels per group
#define EPSV 1e-5f
#define F_QR 0.1f
#define F_KR 0.1f
#define F_SVE 0.1f
#define F_SV  1.0f

// ---------------- scratch (static device allocations) ----------------
__device__ float d_qkv[(size_t)BB * OO * NN];                 // 64 MB
__device__ float d_bnA[OO];
__device__ float d_bnC[OO];
__device__ __half d_stkh[(size_t)3 * BB * GG * NN * NN];      // 201 MB (qk,qr,kr raw, fp16)
__device__ float d_simstats[48];                              // 24 ch x (sum,sumsq)
__device__ float d_sv [(size_t)BB * GG * VC * NN];            // 33.5 MB
__device__ float d_sve[(size_t)BB * GG * VC * NN];            // 33.5 MB
__device__ float d_outA[OO];
__device__ float d_outC[OO];

// ---------------- K0: zero sim stats (must run every replay) ----------------
__global__ void k_zero_stats() {
    int t = threadIdx.x;
    if (t < 48) d_simstats[t] = 0.0f;
}

// ---------------- K1: qkv GEMM  qkv[b][o][n] = sum_c w[o][c]*x[b][n][c] ----------------
// 128x128 tile, GK=8, 256 threads, 8x8 microtile, double-buffered smem.
#define TM 128
#define TO 128
#define TK 8
#define XPAD 4
__global__ __launch_bounds__(256, 2)
void k_qkv_gemm(const float* __restrict__ x, const float* __restrict__ w) {
    __shared__ float Xs[2][TK][TM + XPAD];
    __shared__ float Ws[2][TK][TO + XPAD];
    int b  = blockIdx.z;
    int n0 = blockIdx.x * TM;
    int o0 = blockIdx.y * TO;
    int tid = threadIdx.x;

    // load mapping: each thread loads one float4 of x and one of w per stage
    int lr  = tid >> 1;            // 0..127 (row within tile)
    int lc4 = (tid & 1) * 4;       // 0 or 4 (c offset within 8-wide stage)
    const float* xp = x + ((size_t)b * NN + n0 + lr) * CC + lc4;
    const float* wp = w + (size_t)(o0 + lr) * CC + lc4;

    // compute mapping: 8x8 per thread as two 4-wide chunks in each dim
    int tx = tid & 15;             // n:  tx*4 and 64+tx*4
    int ty = tid >> 4;             // o:  ty*4 and 64+ty*4

    float acc[8][8];
#pragma unroll
    for (int i = 0; i < 8; i++)
#pragma unroll
        for (int j = 0; j < 8; j++) acc[i][j] = 0.0f;

    // prime buffer 0
    {
        float4 xv = *(const float4*)xp;
        float4 wv = *(const float4*)wp;
        Xs[0][lc4 + 0][lr] = xv.x; Xs[0][lc4 + 1][lr] = xv.y;
        Xs[0][lc4 + 2][lr] = xv.z; Xs[0][lc4 + 3][lr] = xv.w;
        Ws[0][lc4 + 0][lr] = wv.x; Ws[0][lc4 + 1][lr] = wv.y;
        Ws[0][lc4 + 2][lr] = wv.z; Ws[0][lc4 + 3][lr] = wv.w;
    }
    __syncthreads();

    int buf = 0;
    for (int c0 = TK; c0 <= CC; c0 += TK) {
        float4 nxv, nwv;
        bool more = (c0 < CC);
        if (more) {
            nxv = *(const float4*)(xp + c0);
            nwv = *(const float4*)(wp + c0);
        }
#pragma unroll
        for (int kk = 0; kk < TK; kk++) {
            float4 a0 = *(const float4*)&Xs[buf][kk][tx * 4];
            float4 a1 = *(const float4*)&Xs[buf][kk][64 + tx * 4];
            float4 b0 = *(const float4*)&Ws[buf][kk][ty * 4];
            float4 b1 = *(const float4*)&Ws[buf][kk][64 + ty * 4];
            float av[8] = {a0.x, a0.y, a0.z, a0.w, a1.x, a1.y, a1.z, a1.w};
            float bv[8] = {b0.x, b0.y, b0.z, b0.w, b1.x, b1.y, b1.z, b1.w};
#pragma unroll
            for (int j = 0; j < 8; j++)
#pragma unroll
                for (int i = 0; i < 8; i++) acc[j][i] += av[i] * bv[j];
        }
        if (more) {
            int nb = buf ^ 1;
            Xs[nb][lc4 + 0][lr] = nxv.x; Xs[nb][lc4 + 1][lr] = nxv.y;
            Xs[nb][lc4 + 2][lr] = nxv.z; Xs[nb][lc4 + 3][lr] = nxv.w;
            Ws[nb][lc4 + 0][lr] = nwv.x; Ws[nb][lc4 + 1][lr] = nwv.y;
            Ws[nb][lc4 + 2][lr] = nwv.z; Ws[nb][lc4 + 3][lr] = nwv.w;
            __syncthreads();
            buf = nb;
        }
    }

    // write out: o rows = o0 + {ty*4+jj, 64+ty*4+jj}, n cols = n0 + {tx*4, 64+tx*4}
    float* outp = d_qkv + ((size_t)b * OO + o0) * NN + n0;
#pragma unroll
    for (int jh = 0; jh < 2; jh++) {
#pragma unroll
        for (int jj = 0; jj < 4; jj++) {
            int j = jh * 4 + jj;
            int orow = jh * 64 + ty * 4 + jj;
            float4 v0 = make_float4(acc[j][0], acc[j][1], acc[j][2], acc[j][3]);
            float4 v1 = make_float4(acc[j][4], acc[j][5], acc[j][6], acc[j][7]);
            *(float4*)(outp + (size_t)orow * NN + tx * 4)      = v0;
            *(float4*)(outp + (size_t)orow * NN + 64 + tx * 4) = v1;
        }
    }
}

// ---------------- block reduce helper ----------------
__device__ __forceinline__ void block_reduce2(float& s, float& ss, float* sh) {
    int tid = threadIdx.x;
    float* shs = sh;         // 256
    float* shq = sh + 256;   // 256
    shs[tid] = s; shq[tid] = ss;
    __syncthreads();
    for (int step = 128; step > 0; step >>= 1) {
        if (tid < step) { shs[tid] += shs[tid + step]; shq[tid] += shq[tid + step]; }
        __syncthreads();
    }
    s = shs[0]; ss = shq[0];
}

// ---------------- K2: qkv BN -> per-channel affine ----------------
__global__ void k_qkv_stats(const float* __restrict__ gq, const float* __restrict__ bq) {
    __shared__ float sh[512];
    int o = blockIdx.x;
    int tid = threadIdx.x;     // n index
    float s = 0.f, ss = 0.f;
    const float* base = d_qkv + (size_t)o * NN + tid;
    for (int b = 0; b < BB; b++) {
        float v = base[(size_t)b * OO * NN];
        s += v; ss += v * v;
    }
    block_reduce2(s, ss, sh);
    if (tid == 0) {
        float m = s / 16384.0f;
        float var = ss / 16384.0f - m * m;
        float a = gq[o] * rsqrtf(var + EPSV);
        d_bnA[o] = a;
        d_bnC[o] = bq[o] - m * a;
    }
}

// ---------------- K3: raw qk/qr/kr + channel stats ----------------
// grid (4 itiles of 64, G, B), 256 threads (thread = j)
__global__ void k_sim_raw(const float* __restrict__ rel) {
    extern __shared__ float sm[];
    float* qs   = sm;                 // 32*64
    float* relA = qs + 32 * 64;       // 32*320
    float* relB = relA + 32 * 320;    // 32*320
    int it = blockIdx.x, g = blockIdx.y, b = blockIdx.z;
    int i0 = it * 64;
    int tid = threadIdx.x;

    for (int idx = tid; idx < 32 * 319; idx += 256) {
        int c = idx / 319, d = idx - c * 319;
        relA[c * 320 + d] = rel[(size_t)c * 511 + i0 + d];
        relB[c * 320 + d] = rel[(size_t)(32 + c) * 511 + (192 - i0) + d];
    }
    {
        int cbase = tid >> 6, il = tid & 63;
        for (int c = cbase; c < 32; c += 4) {
            int o = g * 128 + c;
            qs[c * 64 + il] = d_bnA[o] * d_qkv[((size_t)b * OO + o) * NN + i0 + il] + d_bnC[o];
        }
    }
    float kcol[32];
#pragma unroll
    for (int c = 0; c < 32; c++) {
        int o = g * 128 + HC + c;
        kcol[c] = d_bnA[o] * d_qkv[((size_t)b * OO + o) * NN + tid] + d_bnC[o];
    }
    __syncthreads();

    float s0 = 0, q0 = 0, s1 = 0, q1 = 0, s2 = 0, q2 = 0;
    const size_t F = (size_t)BB * GG * NN * NN;
    size_t base = (((size_t)b * GG + g) * NN + i0) * NN + tid;

    for (int il = 0; il < 64; il++) {
        float aqk = 0.f, aqr = 0.f, akr = 0.f;
        const float* ra = relA + (il + 255 - tid);
        const float* rb = relB + (tid - il + 63);
#pragma unroll
        for (int c = 0; c < 32; c++) {
            float qv = qs[c * 64 + il];
            aqk += qv * kcol[c];
            aqr += qv * ra[c * 320];
            akr += kcol[c] * rb[c * 320];
        }
        aqr *= F_QR; akr *= F_KR;
        size_t off = base + (size_t)il * NN;
        d_stkh[off]         = __float2half_rn(aqk);
        d_stkh[F + off]     = __float2half_rn(aqr);
        d_stkh[2 * F + off] = __float2half_rn(akr);
        s0 += aqk; q0 += aqk * aqk;
        s1 += aqr; q1 += aqr * aqr;
        s2 += akr; q2 += akr * akr;
    }
#pragma unroll
    for (int off = 16; off; off >>= 1) {
        s0 += __shfl_xor_sync(0xffffffffu, s0, off);
        q0 += __shfl_xor_sync(0xffffffffu, q0, off);
        s1 += __shfl_xor_sync(0xffffffffu, s1, off);
        q1 += __shfl_xor_sync(0xffffffffu, q1, off);
        s2 += __shfl_xor_sync(0xffffffffu, s2, off);
        q2 += __shfl_xor_sync(0xffffffffu, q2, off);
    }
    if ((tid & 31) == 0) {
        atomicAdd(&d_simstats[(0 * 8 + g) * 2],     s0);
        atomicAdd(&d_simstats[(0 * 8 + g) * 2 + 1], q0);
        atomicAdd(&d_simstats[(1 * 8 + g) * 2],     s1);
        atomicAdd(&d_simstats[(1 * 8 + g) * 2 + 1], q1);
        atomicAdd(&d_simstats[(2 * 8 + g) * 2],     s2);
        atomicAdd(&d_simstats[(2 * 8 + g) * 2 + 1], q2);
    }
}

// ---------------- K5: sim BN + softmax + sv + sve ----------------
// grid (8 itiles of 32, G, B), 256 threads
__global__ void k_attn(const float* __restrict__ rel,
                       const float* __restrict__ gsim, const float* __restrict__ bsim) {
    extern __shared__ float sm[];
    float* p    = sm;                   // 32*257
    float* vbs  = p + 32 * 257;         // 64*257
    float* relV = vbs + 64 * 257;       // 64*287
    float* stage = relV + 64 * 287;     // 64*33
    int it = blockIdx.x, g = blockIdx.y, b = blockIdx.z;
    int i0 = it * 32;
    int tid = threadIdx.x;

    const float NELI = 1.0f / (64.0f * 256.0f * 256.0f);
    float aS[3], cS[3];
#pragma unroll
    for (int s = 0; s < 3; s++) {
        int ch = s * 8 + g;
        float m = d_simstats[ch * 2] * NELI;
        float var = d_simstats[ch * 2 + 1] * NELI - m * m;
        float a = gsim[ch] * rsqrtf(var + EPSV);
        aS[s] = a; cS[s] = bsim[ch] - m * a;
    }

    const size_t F = (size_t)BB * GG * NN * NN;
    size_t baseL = (((size_t)b * GG + g) * NN + i0) * NN + tid;
    for (int il = 0; il < 32; il++) {
        size_t off = baseL + (size_t)il * NN;
        float L = aS[0] * __half2float(d_stkh[off]) + cS[0]
                + aS[1] * __half2float(d_stkh[F + off]) + cS[1]
                + aS[2] * __half2float(d_stkh[2 * F + off]) + cS[2];
        p[il * 257 + tid] = L;
    }
    for (int c = 0; c < VC; c++) {
        int o = g * 128 + 2 * HC + c;
        vbs[c * 257 + tid] = d_bnA[o] * d_qkv[((size_t)b * OO + o) * NN + tid] + d_bnC[o];
    }
    for (int idx = tid; idx < 64 * 287; idx += 256) {
        int c = idx / 287, d = idx - c * 287;
        relV[idx] = rel[(size_t)(64 + c) * 511 + i0 + d];
    }
    __syncthreads();

    // softmax over j, one warp handles 4 rows
    int warp = tid >> 5, lane = tid & 31;
    for (int r = warp; r < 32; r += 8) {
        float* row = p + r * 257;
        float v[8];
        float mx = -1e30f;
#pragma unroll
        for (int k = 0; k < 8; k++) { v[k] = row[lane + 32 * k]; mx = fmaxf(mx, v[k]); }
#pragma unroll
        for (int off = 16; off; off >>= 1) mx = fmaxf(mx, __shfl_xor_sync(0xffffffffu, mx, off));
        float sum = 0.f;
#pragma unroll
        for (int k = 0; k < 8; k++) { v[k] = expf(v[k] - mx); sum += v[k]; }
#pragma unroll
        for (int off = 16; off; off >>= 1) sum += __shfl_xor_sync(0xffffffffu, sum, off);
        float inv = 1.0f / sum;
#pragma unroll
        for (int k = 0; k < 8; k++) row[lane + 32 * k] = v[k] * inv;
    }
    __syncthreads();

    // sv / sve : thread -> (c = tid%64, il = tid/64 + 4k)
    int c = tid & 63;
    int il0 = tid >> 6;
    float asv[8], asve[8];
#pragma unroll
    for (int k = 0; k < 8; k++) { asv[k] = 0.f; asve[k] = 0.f; }
    for (int j = 0; j < 256; j++) {
        float vb = vbs[c * 257 + j];
#pragma unroll
        for (int k = 0; k < 8; k++) {
            int il = il0 + 4 * k;
            float pv = p[il * 257 + j];
            asv[k]  += pv * vb;
            asve[k] += pv * relV[c * 287 + il + 255 - j];
        }
    }
    size_t baseO = (((size_t)b * GG + g) * VC) * NN + i0;

#pragma unroll
    for (int k = 0; k < 8; k++) stage[c * 33 + il0 + 4 * k] = asv[k] * F_SV;
    __syncthreads();
    for (int idx = tid; idx < 2048; idx += 256) {
        int cc = idx >> 5, ii = idx & 31;
        d_sv[baseO + (size_t)cc * NN + ii] = stage[cc * 33 + ii];
    }
    __syncthreads();
#pragma unroll
    for (int k = 0; k < 8; k++) stage[c * 33 + il0 + 4 * k] = asve[k] * F_SVE;
    __syncthreads();
    for (int idx = tid; idx < 2048; idx += 256) {
        int cc = idx >> 5, ii = idx & 31;
        d_sve[baseO + (size_t)cc * NN + ii] = stage[cc * 33 + ii];
    }
}

// ---------------- K6: out BN stats ----------------
__global__ void k_out_stats(const float* __restrict__ gout, const float* __restrict__ bout) {
    __shared__ float sh[512];
    int ch = blockIdx.x;                  // 0..1023 : ch = g*128 + c*2 + t
    int g = ch >> 7, rem = ch & 127, c = rem >> 1, t = rem & 1;
    int tid = threadIdx.x;                // i index
    const float* src = (t ? d_sve : d_sv) + (((size_t)g) * VC + c) * NN + tid;
    float s = 0.f, ss = 0.f;
    for (int b = 0; b < BB; b++) {
        float v = src[(size_t)b * GG * VC * NN];
        s += v; ss += v * v;
    }
    block_reduce2(s, ss, sh);
    if (tid == 0) {
        float m = s / 16384.0f;
        float var = ss / 16384.0f - m * m;
        float a = gout[ch] * rsqrtf(var + EPSV);
        d_outA[ch] = a;
        d_outC[ch] = bout[ch] - m * a;
    }
}

// ---------------- K7: final combine ----------------
__global__ void k_final(float* __restrict__ out) {
    size_t idx = (size_t)blockIdx.x * 256 + threadIdx.x;   // 64*512*256
    int n = idx & 255;
    int pch = (int)((idx >> 8) & 511);
    int b = (int)(idx >> 17);
    int g = pch >> 6, c = pch & 63;
    size_t si = (((size_t)b * GG + g) * VC + c) * NN + n;
    float sv = d_sv[si], sve = d_sve[si];
    int ch0 = pch * 2, ch1 = ch0 + 1;
    out[idx] = d_outA[ch0] * sv + d_outC[ch0] + d_outA[ch1] * sve + d_outC[ch1];
}

// ---------------- launch ----------------
extern "C" void kernel_launch(void* const* d_in, const int* in_sizes, int n_in,
                              void* d_out, int out_size) {
    const float* x    = (const float*)d_in[0];
    const float* wqkv = (const float*)d_in[1];
    const float* rel  = (const float*)d_in[2];
    const float* gq   = (const float*)d_in[3];
    const float* bq   = (const float*)d_in[4];
    const float* gs   = (const float*)d_in[5];
    const float* bs   = (const float*)d_in[6];
    const float* go   = (const float*)d_in[7];
    const float* bo   = (const float*)d_in[8];
    float* out = (float*)d_out;

    size_t smemK3 = (size_t)(32 * 64 + 2 * 32 * 320) * sizeof(float);          // 90112 B
    size_t smemK5 = (size_t)(32 * 257 + 64 * 257 + 64 * 287 + 64 * 33) * sizeof(float); // ~180.6 KB
    cudaFuncSetAttribute(k_sim_raw, cudaFuncAttributeMaxDynamicSharedMemorySize, (int)smemK3);
    cudaFuncSetAttribute(k_attn,    cudaFuncAttributeMaxDynamicSharedMemorySize, (int)smemK5);

    k_zero_stats<<<1, 64>>>();
    {
        dim3 grid(NN / TM, OO / TO, BB);
        k_qkv_gemm<<<grid, 256>>>(x, wqkv);
    }
    k_qkv_stats<<<OO, 256>>>(gq, bq);
    {
        dim3 grid(4, GG, BB);
        k_sim_raw<<<grid, 256, smemK3>>>(rel);
    }
    {
        dim3 grid(8, GG, BB);
        k_attn<<<grid, 256, smemK5>>>(rel, gs, bs);
    }
    k_out_stats<<<OO, 256>>>(go, bo);
    {
        size_t total = (size_t)BB * 512 * NN;
        k_final<<<(unsigned)(total / 256), 256>>>(out);
    }
}

// round 7
// speedup vs baseline: 2.2482x; 1.3946x over previous
#include <cuda_runtime.h>
#include <cuda_fp16.h>
#include <math.h>

// ---------------- problem constants ----------------
#define BB   64          // batch
#define NN   256         // sequence length (K in reference)
#define CC   512         // input channels
#define OO   1024        // qkv channels (2*OUT_PLANES)
#define GG   8           // groups
#define HC   32          // half group planes (q/k channels per group)
#define VC   64          // v channels per group
#define EPSV 1e-5f
#define F_QR 0.1f
#define F_KR 0.1f
#define F_SVE 0.1f
#define F_SV  1.0f

// ---------------- scratch (static device allocations) ----------------
__device__ float d_qkv[(size_t)BB * OO * NN];                 // 64 MB
__device__ float d_bnA[OO];
__device__ float d_bnC[OO];
__device__ __half d_stkh[(size_t)3 * BB * GG * NN * NN];      // 201 MB (qk,qr,kr raw, fp16)
__device__ float d_simstats[48];                              // 24 ch x (sum,sumsq)
__device__ float d_sv [(size_t)BB * GG * VC * NN];            // 33.5 MB
__device__ float d_sve[(size_t)BB * GG * VC * NN];            // 33.5 MB
__device__ float d_outA[OO];
__device__ float d_outC[OO];

// ---------------- K0: zero sim stats (must run every replay) ----------------
__global__ void k_zero_stats() {
    int t = threadIdx.x;
    if (t < 48) d_simstats[t] = 0.0f;
}

// ---------------- K1: qkv GEMM  qkv[b][o][n] = sum_c w[o][c]*x[b][n][c] ----------------
// 128x128 tile, GK=8, 256 threads, 8x8 microtile, double-buffered smem.
#define TM 128
#define TO 128
#define TK 8
#define XPAD 4
__global__ __launch_bounds__(256, 2)
void k_qkv_gemm(const float* __restrict__ x, const float* __restrict__ w) {
    __shared__ float Xs[2][TK][TM + XPAD];
    __shared__ float Ws[2][TK][TO + XPAD];
    int b  = blockIdx.z;
    int n0 = blockIdx.x * TM;
    int o0 = blockIdx.y * TO;
    int tid = threadIdx.x;

    int lr  = tid >> 1;            // 0..127 (row within tile)
    int lc4 = (tid & 1) * 4;       // 0 or 4
    const float* xp = x + ((size_t)b * NN + n0 + lr) * CC + lc4;
    const float* wp = w + (size_t)(o0 + lr) * CC + lc4;

    int tx = tid & 15;             // n:  tx*4 and 64+tx*4
    int ty = tid >> 4;             // o:  ty*4 and 64+ty*4

    float acc[8][8];
#pragma unroll
    for (int i = 0; i < 8; i++)
#pragma unroll
        for (int j = 0; j < 8; j++) acc[i][j] = 0.0f;

    {
        float4 xv = *(const float4*)xp;
        float4 wv = *(const float4*)wp;
        Xs[0][lc4 + 0][lr] = xv.x; Xs[0][lc4 + 1][lr] = xv.y;
        Xs[0][lc4 + 2][lr] = xv.z; Xs[0][lc4 + 3][lr] = xv.w;
        Ws[0][lc4 + 0][lr] = wv.x; Ws[0][lc4 + 1][lr] = wv.y;
        Ws[0][lc4 + 2][lr] = wv.z; Ws[0][lc4 + 3][lr] = wv.w;
    }
    __syncthreads();

    int buf = 0;
    for (int c0 = TK; c0 <= CC; c0 += TK) {
        float4 nxv, nwv;
        bool more = (c0 < CC);
        if (more) {
            nxv = *(const float4*)(xp + c0);
            nwv = *(const float4*)(wp + c0);
        }
#pragma unroll
        for (int kk = 0; kk < TK; kk++) {
            float4 a0 = *(const float4*)&Xs[buf][kk][tx * 4];
            float4 a1 = *(const float4*)&Xs[buf][kk][64 + tx * 4];
            float4 b0 = *(const float4*)&Ws[buf][kk][ty * 4];
            float4 b1 = *(const float4*)&Ws[buf][kk][64 + ty * 4];
            float av[8] = {a0.x, a0.y, a0.z, a0.w, a1.x, a1.y, a1.z, a1.w};
            float bv[8] = {b0.x, b0.y, b0.z, b0.w, b1.x, b1.y, b1.z, b1.w};
#pragma unroll
            for (int j = 0; j < 8; j++)
#pragma unroll
                for (int i = 0; i < 8; i++) acc[j][i] += av[i] * bv[j];
        }
        if (more) {
            int nb = buf ^ 1;
            Xs[nb][lc4 + 0][lr] = nxv.x; Xs[nb][lc4 + 1][lr] = nxv.y;
            Xs[nb][lc4 + 2][lr] = nxv.z; Xs[nb][lc4 + 3][lr] = nxv.w;
            Ws[nb][lc4 + 0][lr] = nwv.x; Ws[nb][lc4 + 1][lr] = nwv.y;
            Ws[nb][lc4 + 2][lr] = nwv.z; Ws[nb][lc4 + 3][lr] = nwv.w;
            __syncthreads();
            buf = nb;
        }
    }

    float* outp = d_qkv + ((size_t)b * OO + o0) * NN + n0;
#pragma unroll
    for (int jh = 0; jh < 2; jh++) {
#pragma unroll
        for (int jj = 0; jj < 4; jj++) {
            int j = jh * 4 + jj;
            int orow = jh * 64 + ty * 4 + jj;
            float4 v0 = make_float4(acc[j][0], acc[j][1], acc[j][2], acc[j][3]);
            float4 v1 = make_float4(acc[j][4], acc[j][5], acc[j][6], acc[j][7]);
            *(float4*)(outp + (size_t)orow * NN + tx * 4)      = v0;
            *(float4*)(outp + (size_t)orow * NN + 64 + tx * 4) = v1;
        }
    }
}

// ---------------- block reduce helper ----------------
__device__ __forceinline__ void block_reduce2(float& s, float& ss, float* sh) {
    int tid = threadIdx.x;
    float* shs = sh;         // 256
    float* shq = sh + 256;   // 256
    shs[tid] = s; shq[tid] = ss;
    __syncthreads();
    for (int step = 128; step > 0; step >>= 1) {
        if (tid < step) { shs[tid] += shs[tid + step]; shq[tid] += shq[tid + step]; }
        __syncthreads();
    }
    s = shs[0]; ss = shq[0];
}

// ---------------- K2: qkv BN -> per-channel affine ----------------
__global__ void k_qkv_stats(const float* __restrict__ gq, const float* __restrict__ bq) {
    __shared__ float sh[512];
    int o = blockIdx.x;
    int tid = threadIdx.x;     // n index
    float s = 0.f, ss = 0.f;
    const float* base = d_qkv + (size_t)o * NN + tid;
    for (int b = 0; b < BB; b++) {
        float v = base[(size_t)b * OO * NN];
        s += v; ss += v * v;
    }
    block_reduce2(s, ss, sh);
    if (tid == 0) {
        float m = s / 16384.0f;
        float var = ss / 16384.0f - m * m;
        float a = gq[o] * rsqrtf(var + EPSV);
        d_bnA[o] = a;
        d_bnC[o] = bq[o] - m * a;
    }
}

// ---------------- K3: raw qk/qr/kr + channel stats (diagonal register-tiled) ----------------
// block tile: 64 i x 64 j; thread tile 4i x 4j (ti = tid>>4 over i, tj = tid&15 over j)
#define SR_PQ 68      // qs/ks pitch (mod 32 == 4)
#define SR_PR 132     // rel window pitch (mod 32 == 4)
__global__ __launch_bounds__(256, 2)
void k_sim_raw(const float* __restrict__ rel) {
    extern __shared__ float sm[];
    float* qs  = sm;                      // 32 x SR_PQ
    float* ks  = qs + 32 * SR_PQ;         // 32 x SR_PQ
    float* rqa = ks + 32 * SR_PQ;         // 32 x SR_PR (window of rel rows 0..31)
    float* rkb = rqa + 32 * SR_PR;        // 32 x SR_PR (window of rel rows 32..63)
    __shared__ float red[8][6];

    int bx = blockIdx.x;
    int it = bx >> 2, jt = bx & 3;
    int g = blockIdx.y, b = blockIdx.z;
    int i0 = it * 64, j0 = jt * 64;
    int tid = threadIdx.x;

    // rel windows: needed columns: q-side i-j+255 in [offA, offA+126], k-side j-i+255 in [offB, offB+126]
    int offA = 192 + (i0 - j0);
    int offB = 192 + (j0 - i0);
    for (int idx = tid; idx < 32 * 127; idx += 256) {
        int c = idx / 127, t = idx - c * 127;
        rqa[c * SR_PR + t] = rel[(size_t)c * 511 + offA + t];
        rkb[c * SR_PR + t] = rel[(size_t)(32 + c) * 511 + offB + t];
    }
    // q, k tiles with BN affine folded in
    for (int idx = tid; idx < 2048; idx += 256) {
        int c = idx >> 6, v = idx & 63;
        int oq = g * 128 + c;
        int ok = g * 128 + HC + c;
        qs[c * SR_PQ + v] = d_bnA[oq] * d_qkv[((size_t)b * OO + oq) * NN + i0 + v] + d_bnC[oq];
        ks[c * SR_PQ + v] = d_bnA[ok] * d_qkv[((size_t)b * OO + ok) * NN + j0 + v] + d_bnC[ok];
    }
    __syncthreads();

    int ti = tid >> 4, tj = tid & 15;
    float aqk[4][4], aqr[4][4], akr[4][4];
#pragma unroll
    for (int a = 0; a < 4; a++)
#pragma unroll
        for (int e = 0; e < 4; e++) { aqk[a][e] = 0.f; aqr[a][e] = 0.f; akr[a][e] = 0.f; }

    int baseA = 4 * (ti - tj) + 60;   // in [0,120]
    int baseB = 4 * (tj - ti) + 60;

#pragma unroll 2
    for (int c = 0; c < 32; c++) {
        float4 q4  = *(const float4*)&qs[c * SR_PQ + ti * 4];
        float4 k4  = *(const float4*)&ks[c * SR_PQ + tj * 4];
        float4 ra0 = *(const float4*)&rqa[c * SR_PR + baseA];
        float4 ra1 = *(const float4*)&rqa[c * SR_PR + baseA + 4];
        float4 rb0 = *(const float4*)&rkb[c * SR_PR + baseB];
        float4 rb1 = *(const float4*)&rkb[c * SR_PR + baseB + 4];
        float qv[4] = {q4.x, q4.y, q4.z, q4.w};
        float kv[4] = {k4.x, k4.y, k4.z, k4.w};
        float ra[8] = {ra0.x, ra0.y, ra0.z, ra0.w, ra1.x, ra1.y, ra1.z, ra1.w};
        float rb[8] = {rb0.x, rb0.y, rb0.z, rb0.w, rb1.x, rb1.y, rb1.z, rb1.w};
#pragma unroll
        for (int a = 0; a < 4; a++)
#pragma unroll
            for (int e = 0; e < 4; e++) {
                aqk[a][e] += qv[a] * kv[e];
                aqr[a][e] += qv[a] * ra[3 + a - e];   // rel col i-j+255
                akr[a][e] += kv[e] * rb[3 + e - a];   // rel col j-i+255
            }
    }

    // scale + local stats
    float s0 = 0, p0 = 0, s1 = 0, p1 = 0, s2 = 0, p2 = 0;
#pragma unroll
    for (int a = 0; a < 4; a++)
#pragma unroll
        for (int e = 0; e < 4; e++) {
            aqr[a][e] *= F_QR;
            akr[a][e] *= F_KR;
            float v0 = aqk[a][e], v1 = aqr[a][e], v2 = akr[a][e];
            s0 += v0; p0 += v0 * v0;
            s1 += v1; p1 += v1 * v1;
            s2 += v2; p2 += v2 * v2;
        }

    // store fp16, 8B per row per array
    const size_t F = (size_t)BB * GG * NN * NN;
#pragma unroll
    for (int a = 0; a < 4; a++) {
        size_t off = (((size_t)b * GG + g) * NN + i0 + ti * 4 + a) * NN + j0 + tj * 4;
        union { __half2 h2[2]; uint2 u; } pk;
        pk.h2[0] = __floats2half2_rn(aqk[a][0], aqk[a][1]);
        pk.h2[1] = __floats2half2_rn(aqk[a][2], aqk[a][3]);
        *(uint2*)(d_stkh + off) = pk.u;
        pk.h2[0] = __floats2half2_rn(aqr[a][0], aqr[a][1]);
        pk.h2[1] = __floats2half2_rn(aqr[a][2], aqr[a][3]);
        *(uint2*)(d_stkh + F + off) = pk.u;
        pk.h2[0] = __floats2half2_rn(akr[a][0], akr[a][1]);
        pk.h2[1] = __floats2half2_rn(akr[a][2], akr[a][3]);
        *(uint2*)(d_stkh + 2 * F + off) = pk.u;
    }

    // stats: warp reduce -> smem -> 6 atomics per block
#pragma unroll
    for (int off = 16; off; off >>= 1) {
        s0 += __shfl_xor_sync(0xffffffffu, s0, off);
        p0 += __shfl_xor_sync(0xffffffffu, p0, off);
        s1 += __shfl_xor_sync(0xffffffffu, s1, off);
        p1 += __shfl_xor_sync(0xffffffffu, p1, off);
        s2 += __shfl_xor_sync(0xffffffffu, s2, off);
        p2 += __shfl_xor_sync(0xffffffffu, p2, off);
    }
    int warp = tid >> 5, lane = tid & 31;
    if (lane == 0) {
        red[warp][0] = s0; red[warp][1] = p0;
        red[warp][2] = s1; red[warp][3] = p1;
        red[warp][4] = s2; red[warp][5] = p2;
    }
    __syncthreads();
    if (tid < 6) {
        float t = 0.f;
#pragma unroll
        for (int w = 0; w < 8; w++) t += red[w][tid];
        int s = tid >> 1, which = tid & 1;
        atomicAdd(&d_simstats[(s * 8 + g) * 2 + which], t);
    }
}

// ---------------- K5: sim BN + softmax + sv + sve (diagonal register-tiled) ----------------
// grid (8 itiles of 32, G, B), 256 threads; thread = (c = tid&63, il block of 8: il0 = (tid>>6)*8)
#define AT_PP 260     // p pitch
#define AT_PV 260     // vbs pitch
#define AT_PR 324     // relV pitch
__global__ __launch_bounds__(256, 1)
void k_attn(const float* __restrict__ rel,
            const float* __restrict__ gsim, const float* __restrict__ bsim) {
    extern __shared__ float sm[];
    float* p     = sm;                      // 32 x AT_PP
    float* vbs   = p + 32 * AT_PP;          // 64 x AT_PV
    float* relV  = vbs + 64 * AT_PV;        // 64 x AT_PR
    float* stage = relV + 64 * AT_PR;       // 64 x 33
    int it = blockIdx.x, g = blockIdx.y, b = blockIdx.z;
    int i0 = it * 32;
    int tid = threadIdx.x;

    const float NELI = 1.0f / (64.0f * 256.0f * 256.0f);
    float aS[3], cS[3];
#pragma unroll
    for (int s = 0; s < 3; s++) {
        int ch = s * 8 + g;
        float m = d_simstats[ch * 2] * NELI;
        float var = d_simstats[ch * 2 + 1] * NELI - m * m;
        float a = gsim[ch] * rsqrtf(var + EPSV);
        aS[s] = a; cS[s] = bsim[ch] - m * a;
    }

    const size_t F = (size_t)BB * GG * NN * NN;
    size_t baseL = (((size_t)b * GG + g) * NN + i0) * NN + tid;
    for (int il = 0; il < 32; il++) {
        size_t off = baseL + (size_t)il * NN;
        float L = aS[0] * __half2float(d_stkh[off]) + cS[0]
                + aS[1] * __half2float(d_stkh[F + off]) + cS[1]
                + aS[2] * __half2float(d_stkh[2 * F + off]) + cS[2];
        p[il * AT_PP + tid] = L;
    }
    for (int c = 0; c < VC; c++) {
        int o = g * 128 + 2 * HC + c;
        vbs[c * AT_PV + tid] = d_bnA[o] * d_qkv[((size_t)b * OO + o) * NN + tid] + d_bnC[o];
    }
    for (int idx = tid; idx < 64 * 287; idx += 256) {
        int c = idx / 287, d = idx - c * 287;
        relV[c * AT_PR + d] = rel[(size_t)(64 + c) * 511 + i0 + d];
    }
    __syncthreads();

    // softmax over j, one warp per row group
    int warp = tid >> 5, lane = tid & 31;
    for (int r = warp; r < 32; r += 8) {
        float* row = p + r * AT_PP;
        float v[8];
        float mx = -1e30f;
#pragma unroll
        for (int k = 0; k < 8; k++) { v[k] = row[lane + 32 * k]; mx = fmaxf(mx, v[k]); }
#pragma unroll
        for (int off = 16; off; off >>= 1) mx = fmaxf(mx, __shfl_xor_sync(0xffffffffu, mx, off));
        float sum = 0.f;
#pragma unroll
        for (int k = 0; k < 8; k++) { v[k] = expf(v[k] - mx); sum += v[k]; }
#pragma unroll
        for (int off = 16; off; off >>= 1) sum += __shfl_xor_sync(0xffffffffu, sum, off);
        float inv = 1.0f / sum;
#pragma unroll
        for (int k = 0; k < 8; k++) row[lane + 32 * k] = v[k] * inv;
    }
    __syncthreads();

    // sv / sve mainloop: thread -> (c, 8 consecutive il), j in steps of 4
    int c = tid & 63;
    int il0 = (tid >> 6) * 8;     // 0,8,16,24
    float asv[8], asve[8];
#pragma unroll
    for (int k = 0; k < 8; k++) { asv[k] = 0.f; asve[k] = 0.f; }

#pragma unroll 1
    for (int j0 = 0; j0 < 256; j0 += 4) {
        float4 vb4 = *(const float4*)&vbs[c * AT_PV + j0];
        int basev = il0 + 252 - j0;     // >= 0, 4-aligned
        float4 r0 = *(const float4*)&relV[c * AT_PR + basev];
        float4 r1 = *(const float4*)&relV[c * AT_PR + basev + 4];
        float4 r2 = *(const float4*)&relV[c * AT_PR + basev + 8];
        float rr[12] = {r0.x, r0.y, r0.z, r0.w, r1.x, r1.y, r1.z, r1.w,
                        r2.x, r2.y, r2.z, r2.w};
        float vb[4] = {vb4.x, vb4.y, vb4.z, vb4.w};
#pragma unroll
        for (int k = 0; k < 8; k++) {
            float4 p4 = *(const float4*)&p[(il0 + k) * AT_PP + j0];
            float pv[4] = {p4.x, p4.y, p4.z, p4.w};
#pragma unroll
            for (int e = 0; e < 4; e++) {
                asv[k]  += pv[e] * vb[e];
                asve[k] += pv[e] * rr[3 + k - e];   // relV col (il+255-j) - i0... window idx
            }
        }
    }

    size_t baseO = (((size_t)b * GG + g) * VC) * NN + i0;

#pragma unroll
    for (int k = 0; k < 8; k++) stage[c * 33 + il0 + k] = asv[k] * F_SV;
    __syncthreads();
    for (int idx = tid; idx < 2048; idx += 256) {
        int cc = idx >> 5, ii = idx & 31;
        d_sv[baseO + (size_t)cc * NN + ii] = stage[cc * 33 + ii];
    }
    __syncthreads();
#pragma unroll
    for (int k = 0; k < 8; k++) stage[c * 33 + il0 + k] = asve[k] * F_SVE;
    __syncthreads();
    for (int idx = tid; idx < 2048; idx += 256) {
        int cc = idx >> 5, ii = idx & 31;
        d_sve[baseO + (size_t)cc * NN + ii] = stage[cc * 33 + ii];
    }
}

// ---------------- K6: out BN stats ----------------
__global__ void k_out_stats(const float* __restrict__ gout, const float* __restrict__ bout) {
    __shared__ float sh[512];
    int ch = blockIdx.x;                  // 0..1023 : ch = g*128 + c*2 + t
    int g = ch >> 7, rem = ch & 127, c = rem >> 1, t = rem & 1;
    int tid = threadIdx.x;                // i index
    const float* src = (t ? d_sve : d_sv) + (((size_t)g) * VC + c) * NN + tid;
    float s = 0.f, ss = 0.f;
    for (int b = 0; b < BB; b++) {
        float v = src[(size_t)b * GG * VC * NN];
        s += v; ss += v * v;
    }
    block_reduce2(s, ss, sh);
    if (tid == 0) {
        float m = s / 16384.0f;
        float var = ss / 16384.0f - m * m;
        float a = gout[ch] * rsqrtf(var + EPSV);
        d_outA[ch] = a;
        d_outC[ch] = bout[ch] - m * a;
    }
}

// ---------------- K7: final combine ----------------
__global__ void k_final(float* __restrict__ out) {
    size_t idx = (size_t)blockIdx.x * 256 + threadIdx.x;   // 64*512*256
    int n = idx & 255;
    int pch = (int)((idx >> 8) & 511);
    int b = (int)(idx >> 17);
    int g = pch >> 6, c = pch & 63;
    size_t si = (((size_t)b * GG + g) * VC + c) * NN + n;
    float sv = d_sv[si], sve = d_sve[si];
    int ch0 = pch * 2, ch1 = ch0 + 1;
    out[idx] = d_outA[ch0] * sv + d_outC[ch0] + d_outA[ch1] * sve + d_outC[ch1];
}

// ---------------- launch ----------------
extern "C" void kernel_launch(void* const* d_in, const int* in_sizes, int n_in,
                              void* d_out, int out_size) {
    const float* x    = (const float*)d_in[0];
    const float* wqkv = (const float*)d_in[1];
    const float* rel  = (const float*)d_in[2];
    const float* gq   = (const float*)d_in[3];
    const float* bq   = (const float*)d_in[4];
    const float* gs   = (const float*)d_in[5];
    const float* bs   = (const float*)d_in[6];
    const float* go   = (const float*)d_in[7];
    const float* bo   = (const float*)d_in[8];
    float* out = (float*)d_out;

    size_t smemK3 = (size_t)(2 * 32 * SR_PQ + 2 * 32 * SR_PR) * sizeof(float);   // 51200 B
    size_t smemK5 = (size_t)(32 * AT_PP + 64 * AT_PV + 64 * AT_PR + 64 * 33) * sizeof(float); // 191232 B
    cudaFuncSetAttribute(k_sim_raw, cudaFuncAttributeMaxDynamicSharedMemorySize, (int)smemK3);
    cudaFuncSetAttribute(k_attn,    cudaFuncAttributeMaxDynamicSharedMemorySize, (int)smemK5);

    k_zero_stats<<<1, 64>>>();
    {
        dim3 grid(NN / TM, OO / TO, BB);
        k_qkv_gemm<<<grid, 256>>>(x, wqkv);
    }
    k_qkv_stats<<<OO, 256>>>(gq, bq);
    {
        dim3 grid(16, GG, BB);       // 4 i-tiles x 4 j-tiles
        k_sim_raw<<<grid, 256, smemK3>>>(rel);
    }
    {
        dim3 grid(8, GG, BB);
        k_attn<<<grid, 256, smemK5>>>(rel, gs, bs);
    }
    k_out_stats<<<OO, 256>>>(go, bo);
    {
        size_t total = (size_t)BB * 512 * NN;
        k_final<<<(unsigned)(total / 256), 256>>>(out);
    }
}